// round 2
// baseline (speedup 1.0000x reference)
#include <cuda_runtime.h>
#include <cstdint>

#define NB 128
#define ND 1024
#define NC 1024
#define TWO_D 2048
#define NCLS 10
#define ALPHA 1e-3f
#define GAMMA 1e-2f

// ---------------- device scratch (no allocations allowed) ----------------
__device__ float g_coded[NB * TWO_D];          // 1 MB
__device__ float g_tsum[NC];                   // 4 KB
__device__ float g_part[4 * NB * NC];          // 2 MB: [slice][b][c]
__device__ unsigned int g_min_bits, g_max_bits;

// ---------------- cp.async helpers ----------------
__device__ __forceinline__ void cp_async16(uint32_t smem, const void* gmem) {
    asm volatile("cp.async.cg.shared.global [%0], [%1], 16;\n" :: "r"(smem), "l"(gmem));
}
#define CP_COMMIT()  asm volatile("cp.async.commit_group;\n" ::: "memory")
#define CP_WAIT_1()  asm volatile("cp.async.wait_group 1;\n" ::: "memory")
#define CP_WAIT_0()  asm volatile("cp.async.wait_group 0;\n" ::: "memory")

// ---------------- K0: reset reduction state (graph replays!) ----------------
__global__ void k_init() {
    g_min_bits = 0x7f800000u;   // +inf
    g_max_bits = 0u;            // x >= 0, so 0 is a safe -inf for positive floats
}

// ---------------- K1: global min/max of x (exact) ----------------
__global__ void k_minmax(const float* __restrict__ x) {
    const int n = NB * ND;
    float mn = __int_as_float(0x7f800000);
    float mx = 0.0f;
    for (int i = blockIdx.x * blockDim.x + threadIdx.x; i < n; i += gridDim.x * blockDim.x) {
        float v = x[i];
        mn = fminf(mn, v);
        mx = fmaxf(mx, v);
    }
    #pragma unroll
    for (int o = 16; o > 0; o >>= 1) {
        mn = fminf(mn, __shfl_xor_sync(0xffffffffu, mn, o));
        mx = fmaxf(mx, __shfl_xor_sync(0xffffffffu, mx, o));
    }
    __shared__ float s_mn[8], s_mx[8];
    int w = threadIdx.x >> 5, lane = threadIdx.x & 31;
    if (lane == 0) { s_mn[w] = mn; s_mx[w] = mx; }
    __syncthreads();
    if (w == 0) {
        mn = (lane < 8) ? s_mn[lane] : __int_as_float(0x7f800000);
        mx = (lane < 8) ? s_mx[lane] : 0.0f;
        #pragma unroll
        for (int o = 4; o > 0; o >>= 1) {
            mn = fminf(mn, __shfl_xor_sync(0xffffffffu, mn, o));
            mx = fmaxf(mx, __shfl_xor_sync(0xffffffffu, mx, o));
        }
        if (lane == 0) {
            // positive floats: unsigned-int compare == float compare
            atomicMin(&g_min_bits, __float_as_uint(mn));
            atomicMax(&g_max_bits, __float_as_uint(mx));
        }
    }
}

// ---------------- K2: complement-coded normalized input ----------------
__global__ void k_coded(const float* __restrict__ x) {
    int idx = blockIdx.x * blockDim.x + threadIdx.x;
    if (idx >= NB * ND) return;
    float mn = __uint_as_float(g_min_bits);
    float mx = __uint_as_float(g_max_bits);
    float den = (mx - mn) + 1e-10f;
    int b = idx >> 10;
    int j = idx & 1023;
    float xn = (x[idx] - mn) / den;
    g_coded[b * TWO_D + j]        = xn;
    g_coded[b * TWO_D + ND + j]   = 1.0f - xn;
}

// ---------------- K2b: per-template row sums ----------------
__global__ void k_tsum(const float* __restrict__ templates) {
    int w = blockIdx.x * (blockDim.x >> 5) + (threadIdx.x >> 5);  // 512 warps
    int lane = threadIdx.x & 31;
    #pragma unroll
    for (int rr = 0; rr < 2; ++rr) {
        int r = w * 2 + rr;
        const float4* tp = (const float4*)(templates + (size_t)r * TWO_D);
        float s = 0.0f;
        #pragma unroll
        for (int i = 0; i < 16; ++i) {
            float4 v = tp[lane + i * 32];
            s += (v.x + v.y) + (v.z + v.w);
        }
        #pragma unroll
        for (int o = 16; o > 0; o >>= 1) s += __shfl_xor_sync(0xffffffffu, s, o);
        if (lane == 0) g_tsum[r] = s;
    }
}

// ---------------- K3: the min-sum "GEMM" ----------------
// Grid: 128 blocks = 32 c-tiles x 4 j-slices. Block: 256 threads (8 warps).
// Block tile: 128 b x 32 c. Thread tile: 4 b x 4 c. j-slice: 512, staged 32 at a time.
#define KB 32
#define ROWP 36   // padded row length (floats): conflict-free LDS.128
__global__ void __launch_bounds__(256) k_main(const float* __restrict__ templates) {
    __shared__ float sA[2][NB * ROWP];   // 2 x 18KB
    __shared__ float sB[2][32 * ROWP];   // 2 x 4.5KB

    const int tid = threadIdx.x;
    const int ci = blockIdx.x & 31;
    const int sl = blockIdx.x >> 5;           // j-slice 0..3
    const int c0 = ci * 32;
    const int j0 = sl * 512;

    const int w = tid >> 5, lane = tid & 31;
    const int wb = w & 3, wc = w >> 2;        // 4 b-warpgroups x 2 c-warpgroups
    const int b_pos = lane & 7, c_pos = lane >> 3;

    float acc[4][4];
    #pragma unroll
    for (int i = 0; i < 4; ++i)
        #pragma unroll
        for (int k = 0; k < 4; ++k) acc[i][k] = 0.0f;

    uint32_t aBase[2], bBase[2];
    aBase[0] = (uint32_t)__cvta_generic_to_shared(&sA[0][0]);
    aBase[1] = (uint32_t)__cvta_generic_to_shared(&sA[1][0]);
    bBase[0] = (uint32_t)__cvta_generic_to_shared(&sB[0][0]);
    bBase[1] = (uint32_t)__cvta_generic_to_shared(&sB[1][0]);

    auto load_stage = [&](int buf, int jbase) {
        #pragma unroll
        for (int k = 0; k < 4; ++k) {                    // 1024 float4 of coded
            int item = tid + k * 256;
            int row = item >> 3;
            int col = (item & 7) << 2;
            cp_async16(aBase[buf] + (uint32_t)(row * ROWP + col) * 4,
                       g_coded + row * TWO_D + jbase + col);
        }
        {                                                // 256 float4 of templates
            int row = tid >> 3;
            int col = (tid & 7) << 2;
            cp_async16(bBase[buf] + (uint32_t)(row * ROWP + col) * 4,
                       templates + (size_t)(c0 + row) * TWO_D + jbase + col);
        }
    };

    load_stage(0, j0);
    CP_COMMIT();

    #pragma unroll 1
    for (int st = 0; st < 16; ++st) {
        if (st + 1 < 16) {
            load_stage((st + 1) & 1, j0 + (st + 1) * KB);
            CP_COMMIT();
            CP_WAIT_1();
        } else {
            CP_WAIT_0();
        }
        __syncthreads();

        const float* A  = sA[st & 1];
        const float* Bs = sB[st & 1];
        #pragma unroll
        for (int jj = 0; jj < KB; jj += 4) {
            float4 av[4], bv[4];
            #pragma unroll
            for (int ib = 0; ib < 4; ++ib)
                av[ib] = *(const float4*)&A[(wb * 32 + ib * 8 + b_pos) * ROWP + jj];
            #pragma unroll
            for (int ic = 0; ic < 4; ++ic)
                bv[ic] = *(const float4*)&Bs[(wc * 16 + ic * 4 + c_pos) * ROWP + jj];
            #pragma unroll
            for (int ib = 0; ib < 4; ++ib)
                #pragma unroll
                for (int ic = 0; ic < 4; ++ic)
                    acc[ib][ic] += (fminf(av[ib].x, bv[ic].x) + fminf(av[ib].y, bv[ic].y))
                                 + (fminf(av[ib].z, bv[ic].z) + fminf(av[ib].w, bv[ic].w));
        }
        __syncthreads();
    }

    #pragma unroll
    for (int ib = 0; ib < 4; ++ib)
        #pragma unroll
        for (int ic = 0; ic < 4; ++ic) {
            int b = wb * 32 + ib * 8 + b_pos;
            int c = c0 + wc * 16 + ic * 4 + c_pos;
            g_part[(sl * NB + b) * NC + c] = acc[ib][ic];
        }
}

// ---------------- K4: epilogue (choice, argmax, label sums, logits) ----------------
__global__ void k_epilogue(const int* __restrict__ committed,
                           const int* __restrict__ labels,
                           const int* __restrict__ counts,
                           float* __restrict__ out) {
    const int b = blockIdx.x;
    const int tid = threadIdx.x;
    __shared__ float s_bins[NCLS];
    __shared__ float s_val[256];
    __shared__ int   s_idx[256];
    __shared__ int   s_pred;

    if (tid < NCLS) s_bins[tid] = 0.0f;
    __syncthreads();

    const float NEG_INF = __int_as_float(0xff800000);
    float best_v = NEG_INF;
    int best_i = NC;

    #pragma unroll
    for (int k = 0; k < 4; ++k) {
        int c = tid + k * 256;                 // ascending per thread
        float num = ((g_part[(0 * NB + b) * NC + c] + g_part[(1 * NB + b) * NC + c])
                   +  g_part[(2 * NB + b) * NC + c]) + g_part[(3 * NB + b) * NC + c];
        float den = (ALPHA + g_tsum[c]) + GAMMA * (float)counts[c];
        float ch = num / den;
        bool comm = committed[c] != 0;
        float zeroed = comm ? ch : 0.0f;
        atomicAdd(&s_bins[labels[c]], zeroed);
        float mval = comm ? ch : NEG_INF;
        if (mval > best_v) { best_v = mval; best_i = c; }
        else if (mval == best_v && c < best_i) { best_i = c; }
    }
    s_val[tid] = best_v;
    s_idx[tid] = best_i;
    __syncthreads();

    for (int off = 128; off > 0; off >>= 1) {
        if (tid < off) {
            float v2 = s_val[tid + off];
            int   i2 = s_idx[tid + off];
            if (v2 > s_val[tid] || (v2 == s_val[tid] && i2 < s_idx[tid])) {
                s_val[tid] = v2; s_idx[tid] = i2;
            }
        }
        __syncthreads();
    }
    if (tid == 0) s_pred = labels[s_idx[0]];
    __syncthreads();

    if (tid < NCLS)
        out[b * NCLS + tid] = (tid == s_pred) ? s_bins[tid] : 0.0f;
}

// ---------------- launch ----------------
extern "C" void kernel_launch(void* const* d_in, const int* in_sizes, int n_in,
                              void* d_out, int out_size) {
    const float* x         = (const float*)d_in[0];
    const float* templates = (const float*)d_in[1];
    const int*   committed = (const int*)d_in[2];     // bool input -> materialized as int32
    const int*   labels    = (const int*)d_in[3];
    const int*   counts    = (const int*)d_in[4];
    float*       out       = (float*)d_out;

    k_init<<<1, 1>>>();
    k_minmax<<<128, 256>>>(x);
    k_coded<<<512, 256>>>(x);
    k_tsum<<<64, 256>>>(templates);
    k_main<<<128, 256>>>(templates);
    k_epilogue<<<NB, 256>>>(committed, labels, counts, out);
}

// round 3
// speedup vs baseline: 1.2429x; 1.2429x over previous
#include <cuda_runtime.h>
#include <cstdint>

#define NB 128
#define ND 1024
#define NC 1024
#define TWO_D 2048
#define NCLS 10
#define ALPHA 1e-3f
#define GAMMA 1e-2f

// ---------------- device scratch (no allocations allowed) ----------------
__device__ float  g_coded[NB * TWO_D];          // 1 MB
__device__ float  g_tsump[4 * NC];              // 16 KB: per-slice template sums
__device__ float  g_part[4 * NB * NC];          // 2 MB: [slice][b][c]
__device__ float2 g_mm[128];                    // per-block {min,max} partials

// ---------------- cp.async helpers ----------------
__device__ __forceinline__ void cp_async16(uint32_t smem, const void* gmem) {
    asm volatile("cp.async.cg.shared.global [%0], [%1], 16;\n" :: "r"(smem), "l"(gmem));
}
#define CP_COMMIT()  asm volatile("cp.async.commit_group;\n" ::: "memory")
#define CP_WAIT_1()  asm volatile("cp.async.wait_group 1;\n" ::: "memory")
#define CP_WAIT_0()  asm volatile("cp.async.wait_group 0;\n" ::: "memory")

// ---------------- K1: per-block min/max partials (no atomics, no init) ----
__global__ void k_minmax(const float* __restrict__ x) {
    const int n = NB * ND;
    float mn = __int_as_float(0x7f800000);
    float mx = 0.0f;   // x >= 0
    for (int i = blockIdx.x * blockDim.x + threadIdx.x; i < n; i += gridDim.x * blockDim.x) {
        float v = x[i];
        mn = fminf(mn, v);
        mx = fmaxf(mx, v);
    }
    #pragma unroll
    for (int o = 16; o > 0; o >>= 1) {
        mn = fminf(mn, __shfl_xor_sync(0xffffffffu, mn, o));
        mx = fmaxf(mx, __shfl_xor_sync(0xffffffffu, mx, o));
    }
    __shared__ float s_mn[8], s_mx[8];
    int w = threadIdx.x >> 5, lane = threadIdx.x & 31;
    if (lane == 0) { s_mn[w] = mn; s_mx[w] = mx; }
    __syncthreads();
    if (w == 0) {
        mn = (lane < 8) ? s_mn[lane] : __int_as_float(0x7f800000);
        mx = (lane < 8) ? s_mx[lane] : 0.0f;
        #pragma unroll
        for (int o = 4; o > 0; o >>= 1) {
            mn = fminf(mn, __shfl_xor_sync(0xffffffffu, mn, o));
            mx = fmaxf(mx, __shfl_xor_sync(0xffffffffu, mx, o));
        }
        if (lane == 0) g_mm[blockIdx.x] = make_float2(mn, mx);
    }
}

// ---------------- K2: final minmax reduce + complement coding --------------
__global__ void k_coded(const float* __restrict__ x) {
    __shared__ float r_mn[128], r_mx[128];
    const int tid = threadIdx.x;
    if (tid < 128) { float2 v = g_mm[tid]; r_mn[tid] = v.x; r_mx[tid] = v.y; }
    __syncthreads();
    #pragma unroll
    for (int off = 64; off > 0; off >>= 1) {
        if (tid < off) {
            r_mn[tid] = fminf(r_mn[tid], r_mn[tid + off]);
            r_mx[tid] = fmaxf(r_mx[tid], r_mx[tid + off]);
        }
        __syncthreads();
    }
    const float mn = r_mn[0];
    const float den = (r_mx[0] - mn) + 1e-10f;

    int idx = blockIdx.x * blockDim.x + tid;
    if (idx >= NB * ND) return;
    int b = idx >> 10;
    int j = idx & 1023;
    float xn = (x[idx] - mn) / den;
    g_coded[b * TWO_D + j]      = xn;
    g_coded[b * TWO_D + ND + j] = 1.0f - xn;
}

// ---------------- K3: min-sum "GEMM" + fused per-slice template sums -------
// Grid: 128 blocks = 32 c-tiles x 4 j-slices. Block: 256 threads (8 warps).
#define KB 32
#define ROWP 36   // padded row length (floats): conflict-free LDS.128
__global__ void __launch_bounds__(256) k_main(const float* __restrict__ templates) {
    __shared__ float sA[2][NB * ROWP];
    __shared__ float sB[2][32 * ROWP];

    const int tid = threadIdx.x;
    const int ci = blockIdx.x & 31;
    const int sl = blockIdx.x >> 5;           // j-slice 0..3
    const int c0 = ci * 32;
    const int j0 = sl * 512;

    const int w = tid >> 5, lane = tid & 31;
    const int wb = w & 3, wc = w >> 2;
    const int b_pos = lane & 7, c_pos = lane >> 3;

    float acc[4][4];
    #pragma unroll
    for (int i = 0; i < 4; ++i)
        #pragma unroll
        for (int k = 0; k < 4; ++k) acc[i][k] = 0.0f;
    float tsum_acc = 0.0f;

    uint32_t aBase[2], bBase[2];
    aBase[0] = (uint32_t)__cvta_generic_to_shared(&sA[0][0]);
    aBase[1] = (uint32_t)__cvta_generic_to_shared(&sA[1][0]);
    bBase[0] = (uint32_t)__cvta_generic_to_shared(&sB[0][0]);
    bBase[1] = (uint32_t)__cvta_generic_to_shared(&sB[1][0]);

    auto load_stage = [&](int buf, int jbase) {
        #pragma unroll
        for (int k = 0; k < 4; ++k) {
            int item = tid + k * 256;
            int row = item >> 3;
            int col = (item & 7) << 2;
            cp_async16(aBase[buf] + (uint32_t)(row * ROWP + col) * 4,
                       g_coded + row * TWO_D + jbase + col);
        }
        {
            int row = tid >> 3;
            int col = (tid & 7) << 2;
            cp_async16(bBase[buf] + (uint32_t)(row * ROWP + col) * 4,
                       templates + (size_t)(c0 + row) * TWO_D + jbase + col);
        }
    };

    load_stage(0, j0);
    CP_COMMIT();

    #pragma unroll 1
    for (int st = 0; st < 16; ++st) {
        if (st + 1 < 16) {
            load_stage((st + 1) & 1, j0 + (st + 1) * KB);
            CP_COMMIT();
            CP_WAIT_1();
        } else {
            CP_WAIT_0();
        }
        __syncthreads();

        const float* A  = sA[st & 1];
        const float* Bs = sB[st & 1];
        #pragma unroll
        for (int jj = 0; jj < KB; jj += 4) {
            float4 av[4], bv[4];
            #pragma unroll
            for (int ib = 0; ib < 4; ++ib)
                av[ib] = *(const float4*)&A[(wb * 32 + ib * 8 + b_pos) * ROWP + jj];
            #pragma unroll
            for (int ic = 0; ic < 4; ++ic)
                bv[ic] = *(const float4*)&Bs[(wc * 16 + ic * 4 + c_pos) * ROWP + jj];
            #pragma unroll
            for (int ib = 0; ib < 4; ++ib)
                #pragma unroll
                for (int ic = 0; ic < 4; ++ic)
                    acc[ib][ic] += (fminf(av[ib].x, bv[ic].x) + fminf(av[ib].y, bv[ic].y))
                                 + (fminf(av[ib].z, bv[ic].z) + fminf(av[ib].w, bv[ic].w));
        }

        // fused template-row-sum: thread -> (row = tid>>3, 4 cols at (tid&7)*4)
        {
            const float4 tv = *(const float4*)&Bs[(tid >> 3) * ROWP + ((tid & 7) << 2)];
            tsum_acc += (tv.x + tv.y) + (tv.z + tv.w);
        }
        __syncthreads();
    }

    #pragma unroll
    for (int ib = 0; ib < 4; ++ib)
        #pragma unroll
        for (int ic = 0; ic < 4; ++ic) {
            int b = wb * 32 + ib * 8 + b_pos;
            int c = c0 + wc * 16 + ic * 4 + c_pos;
            g_part[(sl * NB + b) * NC + c] = acc[ib][ic];
        }

    // reduce tsum over the 8 threads sharing a row (contiguous lanes)
    #pragma unroll
    for (int o = 4; o > 0; o >>= 1)
        tsum_acc += __shfl_down_sync(0xffffffffu, tsum_acc, o, 8);
    if ((lane & 7) == 0)
        g_tsump[sl * NC + c0 + (tid >> 3)] = tsum_acc;
}

// ---------------- K4: epilogue (choice, argmax, label sums, logits) --------
__global__ void k_epilogue(const int* __restrict__ committed,
                           const int* __restrict__ labels,
                           const int* __restrict__ counts,
                           float* __restrict__ out) {
    const int b = blockIdx.x;
    const int tid = threadIdx.x;
    __shared__ float s_bins[NCLS];
    __shared__ float s_val[256];
    __shared__ int   s_idx[256];
    __shared__ int   s_pred;

    if (tid < NCLS) s_bins[tid] = 0.0f;
    __syncthreads();

    const float NEG_INF = __int_as_float(0xff800000);
    float best_v = NEG_INF;
    int best_i = NC;

    #pragma unroll
    for (int k = 0; k < 4; ++k) {
        int c = tid + k * 256;
        float num = ((g_part[(0 * NB + b) * NC + c] + g_part[(1 * NB + b) * NC + c])
                   +  g_part[(2 * NB + b) * NC + c]) + g_part[(3 * NB + b) * NC + c];
        float ts  = ((g_tsump[0 * NC + c] + g_tsump[1 * NC + c])
                   +  g_tsump[2 * NC + c]) + g_tsump[3 * NC + c];
        float den = (ALPHA + ts) + GAMMA * (float)counts[c];
        float ch = num / den;
        bool comm = committed[c] != 0;
        float zeroed = comm ? ch : 0.0f;
        atomicAdd(&s_bins[labels[c]], zeroed);
        float mval = comm ? ch : NEG_INF;
        if (mval > best_v) { best_v = mval; best_i = c; }
        else if (mval == best_v && c < best_i) { best_i = c; }
    }
    s_val[tid] = best_v;
    s_idx[tid] = best_i;
    __syncthreads();

    for (int off = 128; off > 0; off >>= 1) {
        if (tid < off) {
            float v2 = s_val[tid + off];
            int   i2 = s_idx[tid + off];
            if (v2 > s_val[tid] || (v2 == s_val[tid] && i2 < s_idx[tid])) {
                s_val[tid] = v2; s_idx[tid] = i2;
            }
        }
        __syncthreads();
    }
    if (tid == 0) s_pred = labels[s_idx[0]];
    __syncthreads();

    if (tid < NCLS)
        out[b * NCLS + tid] = (tid == s_pred) ? s_bins[tid] : 0.0f;
}

// ---------------- launch ----------------
extern "C" void kernel_launch(void* const* d_in, const int* in_sizes, int n_in,
                              void* d_out, int out_size) {
    const float* x         = (const float*)d_in[0];
    const float* templates = (const float*)d_in[1];
    const int*   committed = (const int*)d_in[2];   // bool -> int32
    const int*   labels    = (const int*)d_in[3];
    const int*   counts    = (const int*)d_in[4];
    float*       out       = (float*)d_out;

    k_minmax<<<128, 256>>>(x);
    k_coded<<<512, 256>>>(x);
    k_main<<<128, 256>>>(templates);
    k_epilogue<<<NB, 256>>>(committed, labels, counts, out);
}